// round 4
// baseline (speedup 1.0000x reference)
#include <cuda_runtime.h>
#include <cstdint>

#define B_ 32
#define T_ 1024
#define S_ 64
#define D_ 32
#define F_ 64
#define C_ 128
#define NEGV (-1e30f)

// ---------------- scratch (device globals; no runtime alloc) ----------------
__device__ float g_h[10240];          // MLP hidden: [hA 4096 | hD 2048 | hE 4096]
__device__ float g_d[10240];          // MLP out:    [dA 4096 | dD 2048 | dE 4096]
__device__ float g_A[S_ * S_];        // A[s'][s] transition PROBS (row softmax)
__device__ float g_LD[D_ * S_];       // logDur[i][s]  (i = d-1)
__device__ float g_rs[S_ * F_];       // sqrt(1/var)
__device__ float g_mr[S_ * F_];       // mu_c * sqrt(1/var)
__device__ float g_cst[S_];           // sum_f log(var) + F*log(2pi)
__device__ float g_logB[(size_t)B_ * T_ * S_];   // 8 MB, [b][t][s]

// ---------------- helpers ----------------
__device__ __forceinline__ unsigned fkey(float f) {
    unsigned u = __float_as_uint(f);
    return (u >> 31) ? ~u : (u | 0x80000000u);
}
__device__ __forceinline__ float fdec(unsigned k) {
    unsigned u = (k >> 31) ? (k & 0x7fffffffu) : ~k;
    return __uint_as_float(u);
}

// ---------------- K1: h = tanh(W1 @ ctx + b1) for 3 MLPs (warp per row) -----
__global__ void k_mlp1(const float* __restrict__ ctx,
                       const float* __restrict__ aw1, const float* __restrict__ ab1,
                       const float* __restrict__ dw1, const float* __restrict__ db1,
                       const float* __restrict__ ew1, const float* __restrict__ eb1)
{
    int gw   = (blockIdx.x * blockDim.x + threadIdx.x) >> 5;
    int lane = threadIdx.x & 31;
    if (gw >= 10240) return;
    const float* w; const float* bb; int row;
    if (gw < 4096)      { w = aw1; bb = ab1; row = gw; }
    else if (gw < 6144) { w = dw1; bb = db1; row = gw - 4096; }
    else                { w = ew1; bb = eb1; row = gw - 6144; }
    float s = 0.f;
    #pragma unroll
    for (int k = 0; k < 4; k++) {
        int c = lane + 32 * k;
        s += w[(size_t)row * C_ + c] * __ldg(&ctx[c]);
    }
    #pragma unroll
    for (int o = 16; o; o >>= 1) s += __shfl_xor_sync(0xffffffffu, s, o);
    if (lane == 0) g_h[gw] = tanhf(s + bb[row]);
}

// ---------------- K2: d = W2 @ h + b2 (warp per row, float4) ----------------
__global__ void k_mlp2(const float* __restrict__ aw2, const float* __restrict__ ab2,
                       const float* __restrict__ dw2, const float* __restrict__ db2,
                       const float* __restrict__ ew2, const float* __restrict__ eb2)
{
    int gw   = (blockIdx.x * blockDim.x + threadIdx.x) >> 5;
    int lane = threadIdx.x & 31;
    if (gw >= 10240) return;
    const float* w; const float* bb; int row, L, hoff;
    if (gw < 4096)      { w = aw2; bb = ab2; row = gw;        L = 4096; hoff = 0; }
    else if (gw < 6144) { w = dw2; bb = db2; row = gw - 4096; L = 2048; hoff = 4096; }
    else                { w = ew2; bb = eb2; row = gw - 6144; L = 4096; hoff = 6144; }
    const float4* w4 = (const float4*)(w + (size_t)row * L);
    const float4* h4 = (const float4*)(g_h + hoff);
    float s0 = 0.f, s1 = 0.f;
    int n4 = L >> 7;                     // iterations of 128 floats
    for (int k = 0; k < n4; k++) {
        float4 a = __ldg(&w4[lane + 32 * k]);
        float4 h = h4[lane + 32 * k];
        s0 = fmaf(a.x, h.x, s0); s1 = fmaf(a.y, h.y, s1);
        s0 = fmaf(a.z, h.z, s0); s1 = fmaf(a.w, h.w, s1);
    }
    float s = s0 + s1;
    #pragma unroll
    for (int o = 16; o; o >>= 1) s += __shfl_xor_sync(0xffffffffu, s, o);
    if (lane == 0) g_d[gw] = s + bb[row];
}

// ---------------- K3: A probs, logDur, emission params ----------------------
__global__ void k_params(const float* __restrict__ A_logits,
                         const float* __restrict__ D_logits,
                         const float* __restrict__ mu,
                         const float* __restrict__ log_var)
{
    __shared__ float red[64];
    int tid = threadIdx.x, blk = blockIdx.x;
    if (blk < 64) {
        // A row s' = blk : softmax over s of (A_logits + 0.1*tanh(dA))
        int sp = blk;
        float v = A_logits[sp * 64 + tid] + 0.1f * tanhf(g_d[sp * 64 + tid]);
        red[tid] = v; __syncthreads();
        for (int o = 32; o; o >>= 1) { if (tid < o) red[tid] = fmaxf(red[tid], red[tid + o]); __syncthreads(); }
        float m = red[0]; __syncthreads();
        float e = expf(v - m);
        red[tid] = e; __syncthreads();
        for (int o = 32; o; o >>= 1) { if (tid < o) red[tid] += red[tid + o]; __syncthreads(); }
        g_A[sp * 64 + tid] = e / red[0];
    } else if (blk < 128) {
        // Dur row s : log-softmax over d of (D_logits + 0.1*tanh(dD))
        int s = blk - 64;
        if (tid < 32) {
            float v = D_logits[s * 32 + tid] + 0.1f * tanhf(g_d[4096 + s * 32 + tid]);
            float m = v;
            #pragma unroll
            for (int o = 16; o; o >>= 1) m = fmaxf(m, __shfl_xor_sync(0xffffffffu, m, o));
            float e = expf(v - m), sum = e;
            #pragma unroll
            for (int o = 16; o; o >>= 1) sum += __shfl_xor_sync(0xffffffffu, sum, o);
            g_LD[tid * 64 + s] = v - m - logf(sum);
        }
    } else {
        // emission params for state s
        int s = blk - 128, f = tid;
        float mc  = mu[s * 64 + f] + 0.1f * tanhf(g_d[6144 + s * 64 + f]);
        float lv  = log_var[s * 64 + f];
        float sp  = (lv > 20.f) ? lv : log1pf(expf(lv));
        float var = sp + 1e-3f;
        float inv = 1.f / var;
        float r   = sqrtf(inv);
        g_rs[s * 64 + f] = r;
        g_mr[s * 64 + f] = mc * r;
        red[tid] = logf(var); __syncthreads();
        for (int o = 32; o; o >>= 1) { if (tid < o) red[tid] += red[tid + o]; __syncthreads(); }
        if (tid == 0) g_cst[s] = red[0] + 64.f * 1.8378770664093453f;
    }
}

// ---------------- K4: logB[b][t][s] = -0.5*(sum_f (x*rs - mr)^2 + cst) ------
__global__ void __launch_bounds__(128) k_logB(const float* __restrict__ x)
{
    __shared__ float srs[S_ * F_];
    __shared__ float smr[S_ * F_];
    __shared__ float scst[S_];
    int b = blockIdx.y, tb = blockIdx.x, tid = threadIdx.x;
    for (int i = tid; i < S_ * F_; i += 128) { srs[i] = g_rs[i]; smr[i] = g_mr[i]; }
    if (tid < 64) scst[tid] = g_cst[tid];
    __syncthreads();

    int t = tb * 128 + tid;
    float xr[64];
    const float4* xp = (const float4*)(x + ((size_t)(b * T_ + t)) * F_);
    #pragma unroll
    for (int k = 0; k < 16; k++) {
        float4 v = __ldg(&xp[k]);
        xr[4 * k] = v.x; xr[4 * k + 1] = v.y; xr[4 * k + 2] = v.z; xr[4 * k + 3] = v.w;
    }
    float* outp = g_logB + ((size_t)(b * T_ + t)) * S_;
    for (int s = 0; s < S_; s++) {
        const float4* r4 = (const float4*)(srs + s * F_);
        const float4* m4 = (const float4*)(smr + s * F_);
        float a0 = 0.f, a1 = 0.f, a2 = 0.f, a3 = 0.f;
        #pragma unroll
        for (int f4 = 0; f4 < 16; f4++) {
            float4 rv = r4[f4], mv = m4[f4];
            float d0 = fmaf(xr[4 * f4],     rv.x, -mv.x);
            float d1 = fmaf(xr[4 * f4 + 1], rv.y, -mv.y);
            float d2 = fmaf(xr[4 * f4 + 2], rv.z, -mv.z);
            float d3 = fmaf(xr[4 * f4 + 3], rv.w, -mv.w);
            a0 = fmaf(d0, d0, a0); a1 = fmaf(d1, d1, a1);
            a2 = fmaf(d2, d2, a2); a3 = fmaf(d3, d3, a3);
        }
        outp[s] = -0.5f * (((a0 + a1) + (a2 + a3)) + scst[s]);
    }
}

// ---------------- K5: persistent HSMM forward scan (1 CTA per batch) --------
// alpha_t[s] = Ccum[t+1] + lse_d( w_{t-d}[s] + logDur[d,s] ),  w_tau = tr_tau - Ccum[tau+1]
// tr_tau[s]  = lse_{s'}( alpha_tau[s'] + logA[s',s] )  computed as m + log(p . A)
// A held entirely in registers: thread (w,lane) owns A[8w+j][2*lane .. 2*lane+1].
__global__ void __launch_bounds__(256, 1) k_scan(float* __restrict__ out)
{
    __shared__ float    sW[D_ * 65];        // ring of w_tau (padded rows: stride 65)
    __shared__ float    sP[S_];
    __shared__ float    sPart[8 * S_];      // GEMV partials / final reduce
    __shared__ unsigned sKey[2];            // running max(alpha) keys (double-buffered)

    const int b   = blockIdx.x;
    const int tid = threadIdx.x;
    const int s   = tid >> 2;               // 0..63
    const int c   = tid & 3;                // d-chunk 0..3
    const bool sld = (c == 0);              // s-leader
    const int w    = tid >> 5;              // warp 0..7 (GEMV role)
    const int lane = tid & 31;

    // A slice in registers: Areg[2j] = A[8w+j][2*lane], Areg[2j+1] = A[8w+j][2*lane+1]
    float Areg[16];
    #pragma unroll
    for (int j = 0; j < 8; j++) {
        float2 a2 = __ldg(&((const float2*)g_A)[(8 * w + j) * 32 + lane]);
        Areg[2 * j] = a2.x; Areg[2 * j + 1] = a2.y;
    }
    float LDr[8];
    #pragma unroll
    for (int j = 0; j < 8; j++) LDr[j] = g_LD[(c * 8 + j) * S_ + s];
    if (tid < 2) sKey[tid] = 0u;

    const float* lbp = g_logB + ((size_t)b * T_) * S_ + s;
    float Ccum = 0.f, alpha = 0.f, nextLB = 0.f;
    if (sld) nextLB = __ldg(lbp);
    __syncthreads();

    const float LOGPI = -4.1588830833596715f;   // -log(64)

    for (int t = 0; t < T_; t++) {
        if (t > 0) {
            // -------- phase A: tr_{t-1}[s] = m + log(p . A[:,s]); w ring ----
            float m = fdec(sKey[(t - 1) & 1]);
            if (sld) sP[s] = __expf(alpha - m);
            __syncthreads();                                    // S1
            if (tid == 0) sKey[(t - 1) & 1] = 0u;               // reset for t+1
            float4 p0 = ((const float4*)sP)[2 * w];             // broadcast reads
            float4 p1 = ((const float4*)sP)[2 * w + 1];
            float px[8] = {p0.x, p0.y, p0.z, p0.w, p1.x, p1.y, p1.z, p1.w};
            float2 acc = make_float2(0.f, 0.f);
            #pragma unroll
            for (int j = 0; j < 8; j++) {
                acc.x = fmaf(px[j], Areg[2 * j],     acc.x);
                acc.y = fmaf(px[j], Areg[2 * j + 1], acc.y);
            }
            ((float2*)sPart)[w * 32 + lane] = acc;
            __syncthreads();                                    // S2
            if (sld) {
                float sum = 0.f;
                #pragma unroll
                for (int k = 0; k < 8; k++) sum += sPart[k * S_ + s];
                float tr = m + __logf(sum);
                sW[((t - 1) & 31) * 65 + s] = tr - Ccum;        // w_{t-1}
            }
            // NOTE: no barrier here. The only same-step consumer of the
            // w_{t-1} slot is d=1 (chunk c==0), i.e. the writer thread
            // itself; chunks c>=1 read slots written >=8 steps ago, ordered
            // by earlier barriers. The slot-(t&31) overwrite at step t+1 vs
            // its d=32 read at step t is ordered by S4.
        }
        if (sld) {
            Ccum += nextLB;                                     // -> Ccum[t+1]
            if (t + 1 < T_) nextLB = __ldg(lbp + (size_t)(t + 1) * S_);
        }
        // -------- phase B: alpha_t[s] = Ccum[t+1] + lse_d(q[d,s]) ----------
        float q[8], mq = NEGV;
        #pragma unroll
        for (int j = 0; j < 8; j++) {
            int i = c * 8 + j;                                  // i = d-1
            int d = i + 1;
            float qq;
            if (i == t)       qq = LOGPI + LDr[j];              // init, d = t+1
            else if (d <= t)  qq = sW[((t - d) & 31) * 65 + s] + LDr[j];
            else              qq = NEGV;
            q[j] = qq;
            mq = fmaxf(mq, qq);
        }
        mq = fmaxf(mq, __shfl_xor_sync(0xffffffffu, mq, 1));
        mq = fmaxf(mq, __shfl_xor_sync(0xffffffffu, mq, 2));
        float ssum = 0.f;
        #pragma unroll
        for (int j = 0; j < 8; j++) ssum += __expf(q[j] - mq);
        ssum += __shfl_xor_sync(0xffffffffu, ssum, 1);
        ssum += __shfl_xor_sync(0xffffffffu, ssum, 2);
        if (sld) alpha = Ccum + mq + __logf(ssum);
        // warp-level max of alpha (8 distinct s per warp), 1 atomic per warp
        float av = __shfl_sync(0xffffffffu, alpha, (lane & 7) * 4);
        av = fmaxf(av, __shfl_xor_sync(0xffffffffu, av, 1));
        av = fmaxf(av, __shfl_xor_sync(0xffffffffu, av, 2));
        av = fmaxf(av, __shfl_xor_sync(0xffffffffu, av, 4));
        if (lane == 0) atomicMax(&sKey[t & 1], fkey(av));
        __syncthreads();                                        // S4
    }

    // -------- output: out[b] = lse_s(alpha_{T-1}[b,s]) ----------------------
    float m = fdec(sKey[(T_ - 1) & 1]);
    if (sld) sPart[s] = __expf(alpha - m);
    __syncthreads();
    if (tid == 0) {
        float sum = 0.f;
        for (int k = 0; k < S_; k++) sum += sPart[k];
        out[b] = m + logf(sum);
    }
}

// ---------------- launch ----------------------------------------------------
extern "C" void kernel_launch(void* const* d_in, const int* in_sizes, int n_in,
                              void* d_out, int out_size)
{
    const float* x        = (const float*)d_in[0];
    const float* context  = (const float*)d_in[1];
    const float* A_logits = (const float*)d_in[2];
    const float* D_logits = (const float*)d_in[3];
    const float* mu       = (const float*)d_in[4];
    const float* log_var  = (const float*)d_in[5];
    const float* tA_w1 = (const float*)d_in[6];
    const float* tA_b1 = (const float*)d_in[7];
    const float* tA_w2 = (const float*)d_in[8];
    const float* tA_b2 = (const float*)d_in[9];
    const float* tD_w1 = (const float*)d_in[10];
    const float* tD_b1 = (const float*)d_in[11];
    const float* tD_w2 = (const float*)d_in[12];
    const float* tD_b2 = (const float*)d_in[13];
    const float* tE_w1 = (const float*)d_in[14];
    const float* tE_b1 = (const float*)d_in[15];
    const float* tE_w2 = (const float*)d_in[16];
    const float* tE_b2 = (const float*)d_in[17];
    float* out = (float*)d_out;

    k_mlp1<<<1280, 256>>>(context, tA_w1, tA_b1, tD_w1, tD_b1, tE_w1, tE_b1);
    k_mlp2<<<1280, 256>>>(tA_w2, tA_b2, tD_w2, tD_b2, tE_w2, tE_b2);
    k_params<<<192, 64>>>(A_logits, D_logits, mu, log_var);
    {
        dim3 grid(8, 32);
        k_logB<<<grid, 128>>>(x);
    }
    k_scan<<<32, 256>>>(out);
    (void)in_sizes; (void)n_in; (void)out_size;
}

// round 12
// speedup vs baseline: 2.1911x; 2.1911x over previous
#include <cuda_runtime.h>
#include <cstdint>

#define B_ 32
#define T_ 1024
#define S_ 64
#define D_ 32
#define F_ 64
#define C_ 128
#define NEGV (-1e30f)

// ---------------- scratch (device globals; no runtime alloc) ----------------
__device__ float g_h[10240];          // MLP hidden: [hA 4096 | hD 2048 | hE 4096]
__device__ float g_d[10240];          // MLP out:    [dA 4096 | dD 2048 | dE 4096]
__device__ float g_A[S_ * S_];        // A[s'][s] transition PROBS (row softmax)
__device__ float g_LD[D_ * S_];       // logDur[i][s]  (i = d-1)
__device__ float g_rs[S_ * F_];       // sqrt(1/var)
__device__ float g_mr[S_ * F_];       // mu_c * sqrt(1/var)
__device__ float g_cst[S_];           // sum_f log(var) + F*log(2pi)
__device__ float g_logB[(size_t)B_ * T_ * S_];   // 8 MB, [b][t][s]

// ---------------- K1: h = tanh(W1 @ ctx + b1) for 3 MLPs (warp per row) -----
__global__ void k_mlp1(const float* __restrict__ ctx,
                       const float* __restrict__ aw1, const float* __restrict__ ab1,
                       const float* __restrict__ dw1, const float* __restrict__ db1,
                       const float* __restrict__ ew1, const float* __restrict__ eb1)
{
    int gw   = (blockIdx.x * blockDim.x + threadIdx.x) >> 5;
    int lane = threadIdx.x & 31;
    if (gw >= 10240) return;
    const float* w; const float* bb; int row;
    if (gw < 4096)      { w = aw1; bb = ab1; row = gw; }
    else if (gw < 6144) { w = dw1; bb = db1; row = gw - 4096; }
    else                { w = ew1; bb = eb1; row = gw - 6144; }
    float s = 0.f;
    #pragma unroll
    for (int k = 0; k < 4; k++) {
        int c = lane + 32 * k;
        s += w[(size_t)row * C_ + c] * __ldg(&ctx[c]);
    }
    #pragma unroll
    for (int o = 16; o; o >>= 1) s += __shfl_xor_sync(0xffffffffu, s, o);
    if (lane == 0) g_h[gw] = tanhf(s + bb[row]);
}

// ---------------- K2: d = W2 @ h + b2 (warp per row, float4) ----------------
__global__ void k_mlp2(const float* __restrict__ aw2, const float* __restrict__ ab2,
                       const float* __restrict__ dw2, const float* __restrict__ db2,
                       const float* __restrict__ ew2, const float* __restrict__ eb2)
{
    int gw   = (blockIdx.x * blockDim.x + threadIdx.x) >> 5;
    int lane = threadIdx.x & 31;
    if (gw >= 10240) return;
    const float* w; const float* bb; int row, L, hoff;
    if (gw < 4096)      { w = aw2; bb = ab2; row = gw;        L = 4096; hoff = 0; }
    else if (gw < 6144) { w = dw2; bb = db2; row = gw - 4096; L = 2048; hoff = 4096; }
    else                { w = ew2; bb = eb2; row = gw - 6144; L = 4096; hoff = 6144; }
    const float4* w4 = (const float4*)(w + (size_t)row * L);
    const float4* h4 = (const float4*)(g_h + hoff);
    float s0 = 0.f, s1 = 0.f;
    int n4 = L >> 7;
    for (int k = 0; k < n4; k++) {
        float4 a = __ldg(&w4[lane + 32 * k]);
        float4 h = h4[lane + 32 * k];
        s0 = fmaf(a.x, h.x, s0); s1 = fmaf(a.y, h.y, s1);
        s0 = fmaf(a.z, h.z, s0); s1 = fmaf(a.w, h.w, s1);
    }
    float s = s0 + s1;
    #pragma unroll
    for (int o = 16; o; o >>= 1) s += __shfl_xor_sync(0xffffffffu, s, o);
    if (lane == 0) g_d[gw] = s + bb[row];
}

// ---------------- K3: A probs, logDur, emission params ----------------------
__global__ void k_params(const float* __restrict__ A_logits,
                         const float* __restrict__ D_logits,
                         const float* __restrict__ mu,
                         const float* __restrict__ log_var)
{
    __shared__ float red[64];
    int tid = threadIdx.x, blk = blockIdx.x;
    if (blk < 64) {
        int sp = blk;
        float v = A_logits[sp * 64 + tid] + 0.1f * tanhf(g_d[sp * 64 + tid]);
        red[tid] = v; __syncthreads();
        for (int o = 32; o; o >>= 1) { if (tid < o) red[tid] = fmaxf(red[tid], red[tid + o]); __syncthreads(); }
        float m = red[0]; __syncthreads();
        float e = expf(v - m);
        red[tid] = e; __syncthreads();
        for (int o = 32; o; o >>= 1) { if (tid < o) red[tid] += red[tid + o]; __syncthreads(); }
        g_A[sp * 64 + tid] = e / red[0];
    } else if (blk < 128) {
        int s = blk - 64;
        if (tid < 32) {
            float v = D_logits[s * 32 + tid] + 0.1f * tanhf(g_d[4096 + s * 32 + tid]);
            float m = v;
            #pragma unroll
            for (int o = 16; o; o >>= 1) m = fmaxf(m, __shfl_xor_sync(0xffffffffu, m, o));
            float e = expf(v - m), sum = e;
            #pragma unroll
            for (int o = 16; o; o >>= 1) sum += __shfl_xor_sync(0xffffffffu, sum, o);
            g_LD[tid * 64 + s] = v - m - logf(sum);
        }
    } else {
        int s = blk - 128, f = tid;
        float mc  = mu[s * 64 + f] + 0.1f * tanhf(g_d[6144 + s * 64 + f]);
        float lv  = log_var[s * 64 + f];
        float sp  = (lv > 20.f) ? lv : log1pf(expf(lv));
        float var = sp + 1e-3f;
        float inv = 1.f / var;
        float r   = sqrtf(inv);
        g_rs[s * 64 + f] = r;
        g_mr[s * 64 + f] = mc * r;
        red[tid] = logf(var); __syncthreads();
        for (int o = 32; o; o >>= 1) { if (tid < o) red[tid] += red[tid + o]; __syncthreads(); }
        if (tid == 0) g_cst[s] = red[0] + 64.f * 1.8378770664093453f;
    }
}

// ---------------- K4: logB[b][t][s] = -0.5*(sum_f (x*rs - mr)^2 + cst) ------
// z-split over states (2 CTAs per (b,t-tile)); float4 stores.
__global__ void __launch_bounds__(128) k_logB(const float* __restrict__ x)
{
    __shared__ float srs[32 * F_];
    __shared__ float smr[32 * F_];
    __shared__ float scst[32];
    int b = blockIdx.y, tb = blockIdx.x, tid = threadIdx.x;
    int s0 = blockIdx.z * 32;                      // state half
    for (int i = tid; i < 32 * F_; i += 128) {
        srs[i] = g_rs[s0 * F_ + i];
        smr[i] = g_mr[s0 * F_ + i];
    }
    if (tid < 32) scst[tid] = g_cst[s0 + tid];
    __syncthreads();

    int t = tb * 128 + tid;
    float xr[64];
    const float4* xp = (const float4*)(x + ((size_t)(b * T_ + t)) * F_);
    #pragma unroll
    for (int k = 0; k < 16; k++) {
        float4 v = __ldg(&xp[k]);
        xr[4 * k] = v.x; xr[4 * k + 1] = v.y; xr[4 * k + 2] = v.z; xr[4 * k + 3] = v.w;
    }
    float4* outp = (float4*)(g_logB + ((size_t)(b * T_ + t)) * S_ + s0);
    #pragma unroll 2
    for (int sq = 0; sq < 8; sq++) {               // 4 states per iter
        float4 res;
        float* rp = &res.x;
        #pragma unroll
        for (int si = 0; si < 4; si++) {
            int s = sq * 4 + si;
            const float4* r4 = (const float4*)(srs + s * F_);
            const float4* m4 = (const float4*)(smr + s * F_);
            float a0 = 0.f, a1 = 0.f, a2 = 0.f, a3 = 0.f;
            #pragma unroll
            for (int f4 = 0; f4 < 16; f4++) {
                float4 rv = r4[f4], mv = m4[f4];
                float d0 = fmaf(xr[4 * f4],     rv.x, -mv.x);
                float d1 = fmaf(xr[4 * f4 + 1], rv.y, -mv.y);
                float d2 = fmaf(xr[4 * f4 + 2], rv.z, -mv.z);
                float d3 = fmaf(xr[4 * f4 + 3], rv.w, -mv.w);
                a0 = fmaf(d0, d0, a0); a1 = fmaf(d1, d1, a1);
                a2 = fmaf(d2, d2, a2); a3 = fmaf(d3, d3, a3);
            }
            rp[si] = -0.5f * (((a0 + a1) + (a2 + a3)) + scst[s]);
        }
        outp[sq] = res;
    }
}

// ---------------- K5: persistent HSMM forward scan (1 CTA per batch) --------
// ONE __syncthreads per step; no atomics; no leader-only smem chains.
// Lane l of warp w owns state sB = 8w + (l>>2) for ring writes AND phase B.
// GEMV: lane l holds A[2l][8w+j], A[2l+1][8w+j] in regs; reduce-scatter
// butterfly lands output j = (l>>2) on its owner.
// Loop peeled: t<32 prologue (masked), t>=32 steady state (no masks).
__global__ void __launch_bounds__(256, 1) k_scan(float* __restrict__ out)
{
    __shared__ float sW[D_ * 65];                      // ring of w_tau
    __shared__ __align__(16) float sAlpha[2][S_];      // double-buffered alpha
    __shared__ __align__(16) float sWmax[2][8];        // per-warp pivot maxes

    const int b    = blockIdx.x;
    const int tid  = threadIdx.x;
    const int w    = tid >> 5;
    const int lane = tid & 31;
    const int st   = lane >> 2;             // 0..7
    const int sB   = 8 * w + st;            // owned state
    const int c    = lane & 3;              // d-chunk

    // A columns in registers
    float Areg[8], Breg[8];
    #pragma unroll
    for (int j = 0; j < 8; j++) {
        Areg[j] = __ldg(&g_A[(2 * lane)     * S_ + 8 * w + j]);
        Breg[j] = __ldg(&g_A[(2 * lane + 1) * S_ + 8 * w + j]);
    }
    float LDr[8];
    #pragma unroll
    for (int j = 0; j < 8; j++) LDr[j] = __ldg(&g_LD[(c * 8 + j) * S_ + sB]);

    const float* lbp = g_logB + ((size_t)b * T_) * S_ + sB;
    float Ccum = 0.f, wv = 0.f, alpha = NEGV;
    float nextLB = __ldg(lbp);
    __syncthreads();

    const float LOGPI = -4.1588830833596715f;   // -log(64)

    // ---------------- phase A body (t >= 1), shared by both loops ----------
    #define PHASE_A(T)                                                        \
    {                                                                         \
        const int pb = ((T) - 1) & 1;                                         \
        float4 w0 = *(const float4*)(&sWmax[pb][0]);                          \
        float4 w1 = *(const float4*)(&sWmax[pb][4]);                          \
        float m = fmaxf(fmaxf(fmaxf(w0.x, w0.y), fmaxf(w0.z, w0.w)),          \
                        fmaxf(fmaxf(w1.x, w1.y), fmaxf(w1.z, w1.w)));         \
        float2 av = ((const float2*)sAlpha[pb])[lane];                        \
        float p0 = __expf(av.x - m);                                          \
        float p1 = __expf(av.y - m);                                          \
        float acc[8];                                                         \
        _Pragma("unroll")                                                     \
        for (int j = 0; j < 8; j++)                                           \
            acc[j] = fmaf(p0, Areg[j], p1 * Breg[j]);                         \
        float s1v[4];                                                         \
        _Pragma("unroll")                                                     \
        for (int k = 0; k < 4; k++) {                                         \
            float send = (lane & 16) ? acc[k] : acc[k + 4];                   \
            float recv = __shfl_xor_sync(0xffffffffu, send, 16);              \
            float keep = (lane & 16) ? acc[k + 4] : acc[k];                   \
            s1v[k] = keep + recv;                                             \
        }                                                                     \
        float s2v[2];                                                         \
        _Pragma("unroll")                                                     \
        for (int k = 0; k < 2; k++) {                                         \
            float send = (lane & 8) ? s1v[k] : s1v[k + 2];                    \
            float recv = __shfl_xor_sync(0xffffffffu, send, 8);               \
            float keep = (lane & 8) ? s1v[k + 2] : s1v[k];                    \
            s2v[k] = keep + recv;                                             \
        }                                                                     \
        float send = (lane & 4) ? s2v[0] : s2v[1];                            \
        float recv = __shfl_xor_sync(0xffffffffu, send, 4);                   \
        float Ssum = ((lane & 4) ? s2v[1] : s2v[0]) + recv;                   \
        Ssum += __shfl_xor_sync(0xffffffffu, Ssum, 1);                        \
        Ssum += __shfl_xor_sync(0xffffffffu, Ssum, 2);                        \
        wv = m + __logf(Ssum) - Ccum;                                         \
        if (c == 0) sW[(((T) - 1) & 31) * 65 + sB] = wv;                      \
    }

    // ---------------- phase B tail: lse over q[8], pivot, store ------------
    #define PHASE_B_TAIL(T)                                                   \
    {                                                                         \
        mq = fmaxf(mq, __shfl_xor_sync(0xffffffffu, mq, 1));                  \
        mq = fmaxf(mq, __shfl_xor_sync(0xffffffffu, mq, 2));                  \
        float ssum = 0.f;                                                     \
        _Pragma("unroll")                                                     \
        for (int j = 0; j < 8; j++) ssum += __expf(q[j] - mq);                \
        ssum += __shfl_xor_sync(0xffffffffu, ssum, 1);                        \
        ssum += __shfl_xor_sync(0xffffffffu, ssum, 2);                        \
        float pre = Ccum + mq;                                                \
        float pm = pre;                                                       \
        pm = fmaxf(pm, __shfl_xor_sync(0xffffffffu, pm, 4));                  \
        pm = fmaxf(pm, __shfl_xor_sync(0xffffffffu, pm, 8));                  \
        pm = fmaxf(pm, __shfl_xor_sync(0xffffffffu, pm, 16));                 \
        alpha = pre + __logf(ssum);                                           \
        if (c == 0)    sAlpha[(T) & 1][sB] = alpha;                           \
        if (lane == 0) sWmax[(T) & 1][w] = pm;                                \
        __syncthreads();                                                      \
    }

    // -------- prologue: t in [0, 32): masked validity + init term ----------
    for (int t = 0; t < 32; t++) {
        float rv[8];
        #pragma unroll
        for (int j = 0; j < 8; j++) {
            int d = c * 8 + j + 1;
            rv[j] = sW[((t - d) & 31) * 65 + sB];
        }
        if (t > 0) PHASE_A(t)
        Ccum += nextLB;
        nextLB = __ldg(lbp + (size_t)(t + 1) * S_);
        float q[8], mq = NEGV;
        #pragma unroll
        for (int j = 0; j < 8; j++) {
            int i = c * 8 + j;                   // i = d-1
            int d = i + 1;
            float base = (c == 0 && j == 0) ? wv : rv[j];
            float qq;
            if (i == t)       qq = LOGPI + LDr[j];
            else if (d <= t)  qq = base + LDr[j];
            else              qq = NEGV;
            q[j] = qq;
            mq = fmaxf(mq, qq);
        }
        PHASE_B_TAIL(t)
    }

    // -------- steady state: t in [32, T): all d valid, no init -------------
    for (int t = 32; t < T_; t++) {
        float rv[8];
        #pragma unroll
        for (int j = 0; j < 8; j++) {
            int d = c * 8 + j + 1;
            rv[j] = sW[((t - d) & 31) * 65 + sB];
        }
        PHASE_A(t)
        Ccum += nextLB;
        if (t + 1 < T_) nextLB = __ldg(lbp + (size_t)(t + 1) * S_);
        float q[8], mq = NEGV;
        if (c == 0) rv[0] = wv;                  // register-forward d=1
        #pragma unroll
        for (int j = 0; j < 8; j++) {
            q[j] = rv[j] + LDr[j];
            mq = fmaxf(mq, q[j]);
        }
        PHASE_B_TAIL(t)
    }

    #undef PHASE_A
    #undef PHASE_B_TAIL

    // ---- output: out[b] = lse_s(alpha_{T-1}[b,s]) ----
    if (w == 0) {
        float2 av = ((const float2*)sAlpha[(T_ - 1) & 1])[lane];
        float mm = fmaxf(av.x, av.y);
        #pragma unroll
        for (int o = 16; o; o >>= 1) mm = fmaxf(mm, __shfl_xor_sync(0xffffffffu, mm, o));
        float ss = __expf(av.x - mm) + __expf(av.y - mm);
        #pragma unroll
        for (int o = 16; o; o >>= 1) ss += __shfl_xor_sync(0xffffffffu, ss, o);
        if (lane == 0) out[b] = mm + logf(ss);
    }
}

// ---------------- launch ----------------------------------------------------
extern "C" void kernel_launch(void* const* d_in, const int* in_sizes, int n_in,
                              void* d_out, int out_size)
{
    const float* x        = (const float*)d_in[0];
    const float* context  = (const float*)d_in[1];
    const float* A_logits = (const float*)d_in[2];
    const float* D_logits = (const float*)d_in[3];
    const float* mu       = (const float*)d_in[4];
    const float* log_var  = (const float*)d_in[5];
    const float* tA_w1 = (const float*)d_in[6];
    const float* tA_b1 = (const float*)d_in[7];
    const float* tA_w2 = (const float*)d_in[8];
    const float* tA_b2 = (const float*)d_in[9];
    const float* tD_w1 = (const float*)d_in[10];
    const float* tD_b1 = (const float*)d_in[11];
    const float* tD_w2 = (const float*)d_in[12];
    const float* tD_b2 = (const float*)d_in[13];
    const float* tE_w1 = (const float*)d_in[14];
    const float* tE_b1 = (const float*)d_in[15];
    const float* tE_w2 = (const float*)d_in[16];
    const float* tE_b2 = (const float*)d_in[17];
    float* out = (float*)d_out;

    k_mlp1<<<1280, 256>>>(context, tA_w1, tA_b1, tD_w1, tD_b1, tE_w1, tE_b1);
    k_mlp2<<<1280, 256>>>(tA_w2, tA_b2, tD_w2, tD_b2, tE_w2, tE_b2);
    k_params<<<192, 64>>>(A_logits, D_logits, mu, log_var);
    {
        dim3 grid(8, 32, 2);
        k_logB<<<grid, 128>>>(x);
    }
    k_scan<<<32, 256>>>(out);
    (void)in_sizes; (void)n_in; (void)out_size;
}